// round 10
// baseline (speedup 1.0000x reference)
#include <cuda_runtime.h>
#include <cstdint>

#define BB 32
#define SS 1024
#define DD 64
#define TQ 64
#define TK 64
#define NT 128

#define KS_STRIDE 68
#define VS_STRIDE 72
#define RP_STRIDE 129
#define PT_STRIDE 136

// smem float offsets
#define KS_OFF  0                            // K tf32, 64 x 68
#define VS0_OFF (KS_OFF + 64*KS_STRIDE)      // 4352  V raw fp32 buf0, 64 x 72
#define VS1_OFF (VS0_OFF + 64*VS_STRIDE)     // 8960  V raw fp32 buf1
#define RP_OFF  (VS1_OFF + 64*VS_STRIDE)     // 13568
#define SMEM_FLOATS (RP_OFF + 64*RP_STRIDE)  // 21824 floats = 87296 B -> 2 CTAs/SM
#define PT_OFF KS_OFF                        // ptt aliases K+V0+V1 region (8704 <= 13568)

__device__ __forceinline__ unsigned f2tf(float f) {
    unsigned u; asm("cvt.rna.tf32.f32 %0, %1;" : "=r"(u) : "f"(f)); return u;
}
__device__ __forceinline__ void mma_tf32(float c[4], const unsigned a[4],
                                         unsigned b0, unsigned b1) {
    asm volatile(
        "mma.sync.aligned.m16n8k8.row.col.f32.tf32.tf32.f32 "
        "{%0,%1,%2,%3}, {%4,%5,%6,%7}, {%8,%9}, {%0,%1,%2,%3};"
        : "+f"(c[0]), "+f"(c[1]), "+f"(c[2]), "+f"(c[3])
        : "r"(a[0]), "r"(a[1]), "r"(a[2]), "r"(a[3]), "r"(b0), "r"(b1));
}
__device__ __forceinline__ void cpa16(unsigned s, const void* g) {
    asm volatile("cp.async.cg.shared.global [%0], [%1], 16;" :: "r"(s), "l"(g));
}
#define CP_COMMIT() asm volatile("cp.async.commit_group;")
#define CP_WAIT(n)  asm volatile("cp.async.wait_group %0;" :: "n"(n))

// pack 16 ints (4 int4) into 16 mask bits
__device__ __forceinline__ unsigned pack16(const int4* m4) {
    unsigned bits = 0;
    #pragma unroll
    for (int l = 0; l < 4; l++) {
        int4 v = m4[l];
        unsigned nib = (unsigned)(v.x != 0) | ((unsigned)(v.y != 0) << 1)
                     | ((unsigned)(v.z != 0) << 2) | ((unsigned)(v.w != 0) << 3);
        bits |= nib << (4 * l);
    }
    return bits;
}

// rp-table GEMM chunk: stores PRE-SCALED values rp'[r][j] = (q[r,:].pt[j,:])*0.125 - 16
template<int NB0, int NBN>
__device__ __forceinline__ void rp_mma_chunk(const unsigned aq[8][4], const float* ptt,
                                             float* rp, int r0, int r1, int u, int g) {
    float c[NBN][4];
    #pragma unroll
    for (int n = 0; n < NBN; n++) { c[n][0]=0.f; c[n][1]=0.f; c[n][2]=0.f; c[n][3]=0.f; }
    #pragma unroll
    for (int s = 0; s < 8; s++) {
        #pragma unroll
        for (int n = 0; n < NBN; n++) {
            int jr = (NB0 + n) * 8 + g;
            unsigned b0 = __float_as_uint(ptt[(8*s + u)     * PT_STRIDE + jr]);
            unsigned b1 = __float_as_uint(ptt[(8*s + u + 4) * PT_STRIDE + jr]);
            mma_tf32(c[n], aq[s], b0, b1);
        }
    }
    #pragma unroll
    for (int n = 0; n < NBN; n++) {
        int col = (NB0 + n) * 8 + 2 * u;
        if (col <= 128) {
            rp[r0*RP_STRIDE + col] = fmaf(c[n][0], 0.125f, -16.f);
            rp[r1*RP_STRIDE + col] = fmaf(c[n][2], 0.125f, -16.f);
        }
        if (col + 1 <= 128) {
            rp[r0*RP_STRIDE + col + 1] = fmaf(c[n][1], 0.125f, -16.f);
            rp[r1*RP_STRIDE + col + 1] = fmaf(c[n][3], 0.125f, -16.f);
        }
    }
}

__global__ void __launch_bounds__(NT, 2)
attn_tc_kernel(const float* __restrict__ q,
               const float* __restrict__ k,
               const float* __restrict__ v,
               const int* __restrict__ mask,
               const float* __restrict__ pt,
               float* __restrict__ out) {
    extern __shared__ float sm[];
    float* ks  = sm + KS_OFF;
    float* rp  = sm + RP_OFF;
    float* ptt = sm + PT_OFF;

    const int tid  = threadIdx.x;
    const int lane = tid & 31;
    const int w    = tid >> 5;
    const int u    = lane & 3;
    const int g    = lane >> 2;
    const int qt   = blockIdx.x, b = blockIdx.y;
    const int qg0  = qt * TQ;
    const int r0   = 16 * w + g;
    const int r1   = r0 + 8;
    const int keysel = (g >> 1) + 4 * (g & 1);   // sigma(g)

    const float4* kg = (const float4*)(k + (size_t)b * SS * DD);
    const float4* vg = (const float4*)(v + (size_t)b * SS * DD);
    const int* mrow0 = mask + (size_t)(b * SS + qg0 + r0) * SS;
    const int* mrow1 = mask + (size_t)(b * SS + qg0 + r1) * SS;

    // ---- phase 0: stage transposed tf32 pos_table (aliases K/V region) ----
    {
        const float4* ptg = (const float4*)pt;
        for (int i = tid; i < 129 * 16; i += NT) {
            int j = i >> 4, c0 = (i & 15) * 4;
            float4 p4 = ptg[i];
            ptt[(c0 + 0) * PT_STRIDE + j] = __uint_as_float(f2tf(p4.x));
            ptt[(c0 + 1) * PT_STRIDE + j] = __uint_as_float(f2tf(p4.y));
            ptt[(c0 + 2) * PT_STRIDE + j] = __uint_as_float(f2tf(p4.z));
            ptt[(c0 + 3) * PT_STRIDE + j] = __uint_as_float(f2tf(p4.w));
        }
        for (int i = tid; i < 64 * 7; i += NT)
            ptt[(i / 7) * PT_STRIDE + 129 + (i % 7)] = 0.f;
    }

    // ---- Q fragments straight from gmem ----
    unsigned aq[8][4];
    {
        const float* q0 = q + (size_t)(b * SS + qg0 + r0) * DD;
        const float* q1 = q + (size_t)(b * SS + qg0 + r1) * DD;
        #pragma unroll
        for (int s = 0; s < 8; s++) {
            aq[s][0] = f2tf(q0[8*s + u]);
            aq[s][1] = f2tf(q1[8*s + u]);
            aq[s][2] = f2tf(q0[8*s + u + 4]);
            aq[s][3] = f2tf(q1[8*s + u + 4]);
        }
    }
    __syncthreads();

    // ---- phase 1: rp table via MMA (pre-scaled: *0.125 - 16) ----
    rp_mma_chunk<0, 9>(aq, ptt, rp, r0, r1, u, g);
    rp_mma_chunk<9, 8>(aq, ptt, rp, r0, r1, u, g);
    __syncthreads();

    const float rpn0 = rp[r0 * RP_STRIDE + 0],   rpn1 = rp[r1 * RP_STRIDE + 0];
    const float rpp0 = rp[r0 * RP_STRIDE + 128], rpp1 = rp[r1 * RP_STRIDE + 128];

    // ---- prologue staging: cp.async V0 (raw), direct K0 (cvt+STS), mask tile 0 ----
    int4 mm0[4], mm1[4];           // mask prefetch registers (one tile ahead)
    {
        #pragma unroll
        for (int l = 0; l < 8; l++) {
            int i = tid + l * NT, row = i >> 4, c4 = i & 15;
            unsigned dst = (unsigned)__cvta_generic_to_shared(sm + VS0_OFF + row * VS_STRIDE + c4 * 4);
            cpa16(dst, vg + i);
        }
        CP_COMMIT();
        {
            const int4* p0 = (const int4*)(mrow0) + 4 * u;
            const int4* p1 = (const int4*)(mrow1) + 4 * u;
            #pragma unroll
            for (int l = 0; l < 4; l++) { mm0[l] = p0[l]; mm1[l] = p1[l]; }
        }
        #pragma unroll
        for (int l = 0; l < 8; l++) {
            int i = tid + l * NT, row = i >> 4, c4 = i & 15;
            float4 kv = kg[i];
            float* kd = ks + row * KS_STRIDE + c4 * 4;
            kd[0] = __uint_as_float(f2tf(kv.x)); kd[1] = __uint_as_float(f2tf(kv.y));
            kd[2] = __uint_as_float(f2tf(kv.z)); kd[3] = __uint_as_float(f2tf(kv.w));
        }
        CP_WAIT(0);
    }
    __syncthreads();

    float ps0 = 0.f, ps1 = 0.f;    // per-thread softmax denominators
    float co[8][4];
    #pragma unroll
    for (int j = 0; j < 8; j++) { co[j][0]=0.f; co[j][1]=0.f; co[j][2]=0.f; co[j][3]=0.f; }

    float4 pk[8];

    for (int kt = 0; kt < SS / TK; kt++) {
        const int kg0 = kt * TK;
        const int D   = kg0 - qg0;
        const float* vcur = sm + ((kt & 1) ? VS1_OFF : VS0_OFF);

        // ---- pack CURRENT tile's mask words (data loaded one tile ago) ----
        unsigned mw0a, mw0b, mw1a, mw1b;
        {
            unsigned b0 = pack16(mm0) << ((u & 1) * 16);
            unsigned b1 = pack16(mm1) << ((u & 1) * 16);
            b0 |= __shfl_xor_sync(0xffffffffu, b0, 1);
            b1 |= __shfl_xor_sync(0xffffffffu, b1, 1);
            unsigned o0 = __shfl_xor_sync(0xffffffffu, b0, 2);
            unsigned o1 = __shfl_xor_sync(0xffffffffu, b1, 2);
            mw0a = (u & 2) ? o0 : b0;  mw0b = (u & 2) ? b0 : o0;
            mw1a = (u & 2) ? o1 : b1;  mw1b = (u & 2) ? b1 : o1;
        }

        // ---- issue NEXT tile's mask LDGs (full-tile latency distance) ----
        if (kt < 15) {
            const int4* p0 = (const int4*)(mrow0 + kg0 + TK) + 4 * u;
            const int4* p1 = (const int4*)(mrow1 + kg0 + TK) + 4 * u;
            #pragma unroll
            for (int l = 0; l < 4; l++) { mm0[l] = p0[l]; mm1[l] = p1[l]; }
        }

        // ---- issue next tile: V via cp.async, K into registers ----
        if (kt < 15) {
            float* vnext = sm + (((kt + 1) & 1) ? VS1_OFF : VS0_OFF);
            #pragma unroll
            for (int l = 0; l < 8; l++) {
                int i = tid + l * NT, row = i >> 4, c4 = i & 15;
                unsigned dst = (unsigned)__cvta_generic_to_shared(vnext + row * VS_STRIDE + c4 * 4);
                cpa16(dst, vg + (kg0 + TK) * 16 + i);
            }
            #pragma unroll
            for (int l = 0; l < 8; l++)
                pk[l] = kg[(kg0 + TK) * 16 + tid + l * NT];
        }
        CP_COMMIT();

        // ---- QK^T from staged K ----
        float c[8][4];
        #pragma unroll
        for (int j = 0; j < 8; j++) { c[j][0]=0.f; c[j][1]=0.f; c[j][2]=0.f; c[j][3]=0.f; }
        #pragma unroll
        for (int s = 0; s < 8; s++) {
            #pragma unroll
            for (int j = 0; j < 8; j++) {
                unsigned b0 = __float_as_uint(ks[(8*j + keysel) * KS_STRIDE + 8*s + u]);
                unsigned b1 = __float_as_uint(ks[(8*j + keysel) * KS_STRIDE + 8*s + u + 4]);
                mma_tf32(c[j], aq[s], b0, b1);
            }
        }

        // ---- epilogue: p = exp(dot*0.125 + rp')   [rp' has -16 folded in] ----
        const bool nearT = (D >= -64) && (D <= 64);
        #pragma unroll
        for (int j = 0; j < 8; j++) {
            const int col0 = 8*j + u, col1 = col0 + 4;
            float rv00, rv01, rv10, rv11;
            if (nearT) {
                int i00 = min(max(D + col0 - r0, -64), 64) + 64;
                int i01 = min(max(D + col1 - r0, -64), 64) + 64;
                int i10 = min(max(D + col0 - r1, -64), 64) + 64;
                int i11 = min(max(D + col1 - r1, -64), 64) + 64;
                rv00 = rp[r0 * RP_STRIDE + i00]; rv01 = rp[r0 * RP_STRIDE + i01];
                rv10 = rp[r1 * RP_STRIDE + i10]; rv11 = rp[r1 * RP_STRIDE + i11];
            } else if (D > 0) {
                rv00 = rpp0; rv01 = rpp0; rv10 = rpp1; rv11 = rpp1;
            } else {
                rv00 = rpn0; rv01 = rpn0; rv10 = rpn1; rv11 = rpn1;
            }
            const unsigned w0 = (j < 4) ? mw0a : mw0b;
            const unsigned w1 = (j < 4) ? mw1a : mw1b;
            float p00 = ((w0 >> (col0 & 31)) & 1) ? 0.f : __expf(fmaf(c[j][0], 0.125f, rv00));
            float p01 = ((w0 >> (col1 & 31)) & 1) ? 0.f : __expf(fmaf(c[j][1], 0.125f, rv01));
            float p10 = ((w1 >> (col0 & 31)) & 1) ? 0.f : __expf(fmaf(c[j][2], 0.125f, rv10));
            float p11 = ((w1 >> (col1 & 31)) & 1) ? 0.f : __expf(fmaf(c[j][3], 0.125f, rv11));
            ps0 += p00 + p01;
            ps1 += p10 + p11;
            c[j][0] = p00; c[j][1] = p01; c[j][2] = p10; c[j][3] = p11;
        }

        // ---- V[kt] landed; make visible; stage K[kt+1] from prefetch regs ----
        CP_WAIT(1);
        __syncthreads();
        if (kt < 15) {
            #pragma unroll
            for (int l = 0; l < 8; l++) {
                int i = tid + l * NT, row = i >> 4, c4 = i & 15;
                float* kd = ks + row * KS_STRIDE + c4 * 4;
                kd[0] = __uint_as_float(f2tf(pk[l].x)); kd[1] = __uint_as_float(f2tf(pk[l].y));
                kd[2] = __uint_as_float(f2tf(pk[l].z)); kd[3] = __uint_as_float(f2tf(pk[l].w));
            }
        }

        // ---- PV: A frags renamed from P; V converted at fragment load ----
        #pragma unroll
        for (int s = 0; s < 8; s++) {
            unsigned a[4] = { f2tf(c[s][0]), f2tf(c[s][2]), f2tf(c[s][1]), f2tf(c[s][3]) };
            #pragma unroll
            for (int j = 0; j < 8; j++) {
                unsigned b0 = f2tf(vcur[(8*s + u)     * VS_STRIDE + 8*j + g]);
                unsigned b1 = f2tf(vcur[(8*s + u + 4) * VS_STRIDE + 8*j + g]);
                mma_tf32(co[j], a, b0, b1);
            }
        }
        __syncthreads();   // K STS visible before next QK; V buffer free for reuse
    }

    // ---- single softmax-denominator reduction (quad) ----
    ps0 += __shfl_xor_sync(0xffffffffu, ps0, 1);
    ps0 += __shfl_xor_sync(0xffffffffu, ps0, 2);
    ps1 += __shfl_xor_sync(0xffffffffu, ps1, 1);
    ps1 += __shfl_xor_sync(0xffffffffu, ps1, 2);

    // ---- finalize ----
    const float il0 = 1.0f / ps0, il1 = 1.0f / ps1;
    float* o0 = out + (size_t)(b * SS + qg0 + r0) * DD;
    float* o1 = out + (size_t)(b * SS + qg0 + r1) * DD;
    #pragma unroll
    for (int j = 0; j < 8; j++) {
        int col = 8*j + 2*u;
        float2 v0; v0.x = co[j][0] * il0; v0.y = co[j][1] * il0;
        float2 v1; v1.x = co[j][2] * il1; v1.y = co[j][3] * il1;
        *(float2*)(o0 + col) = v0;
        *(float2*)(o1 + col) = v1;
    }
}

extern "C" void kernel_launch(void* const* d_in, const int* in_sizes, int n_in,
                              void* d_out, int out_size) {
    const float* q    = (const float*)d_in[0];
    const float* k    = (const float*)d_in[1];
    const float* v    = (const float*)d_in[2];
    const int*   mask = (const int*)d_in[3];
    const float* pt   = (const float*)d_in[4];
    float*       out  = (float*)d_out;

    size_t smem = SMEM_FLOATS * sizeof(float);
    cudaFuncSetAttribute(attn_tc_kernel,
                         cudaFuncAttributeMaxDynamicSharedMemorySize, (int)smem);
    dim3 grid(SS / TQ, BB);
    attn_tc_kernel<<<grid, NT, smem>>>(q, k, v, mask, pt, out);
}

// round 11
// speedup vs baseline: 1.2549x; 1.2549x over previous
#include <cuda_runtime.h>
#include <cstdint>

#define BB 32
#define SS 1024
#define DD 64
#define TQ 64
#define TK 64
#define NT 128

#define KS_STRIDE 68
#define VS_STRIDE 72
#define RP_STRIDE 129
#define PT_STRIDE 136

// smem float offsets
#define KS_OFF  0                            // K tf32, 64 x 68
#define VS0_OFF (KS_OFF + 64*KS_STRIDE)      // 4352  V raw fp32 buf0, 64 x 72
#define VS1_OFF (VS0_OFF + 64*VS_STRIDE)     // 8960  V raw fp32 buf1
#define RP_OFF  (VS1_OFF + 64*VS_STRIDE)     // 13568
#define SMEM_FLOATS (RP_OFF + 64*RP_STRIDE)  // 21824 floats = 87296 B -> 2 CTAs/SM
#define PT_OFF KS_OFF                        // ptt aliases K+V0+V1 region (8704 <= 13568)

__device__ __forceinline__ unsigned f2tf(float f) {
    unsigned u; asm("cvt.rna.tf32.f32 %0, %1;" : "=r"(u) : "f"(f)); return u;
}
__device__ __forceinline__ void mma_tf32(float c[4], const unsigned a[4],
                                         unsigned b0, unsigned b1) {
    asm volatile(
        "mma.sync.aligned.m16n8k8.row.col.f32.tf32.tf32.f32 "
        "{%0,%1,%2,%3}, {%4,%5,%6,%7}, {%8,%9}, {%0,%1,%2,%3};"
        : "+f"(c[0]), "+f"(c[1]), "+f"(c[2]), "+f"(c[3])
        : "r"(a[0]), "r"(a[1]), "r"(a[2]), "r"(a[3]), "r"(b0), "r"(b1));
}
__device__ __forceinline__ void cpa16(unsigned s, const void* g) {
    asm volatile("cp.async.cg.shared.global [%0], [%1], 16;" :: "r"(s), "l"(g));
}
#define CP_COMMIT() asm volatile("cp.async.commit_group;")
#define CP_WAIT(n)  asm volatile("cp.async.wait_group %0;" :: "n"(n))

// pack 16 ints (4 int4) into 16 mask bits
__device__ __forceinline__ unsigned pack16(const int4* m4) {
    unsigned bits = 0;
    #pragma unroll
    for (int l = 0; l < 4; l++) {
        int4 v = m4[l];
        unsigned nib = (unsigned)(v.x != 0) | ((unsigned)(v.y != 0) << 1)
                     | ((unsigned)(v.z != 0) << 2) | ((unsigned)(v.w != 0) << 3);
        bits |= nib << (4 * l);
    }
    return bits;
}

// rp-table GEMM chunk: stores PRE-SCALED values rp'[r][j] = (q[r,:].pt[j,:])*0.125 - 16
template<int NB0, int NBN>
__device__ __forceinline__ void rp_mma_chunk(const unsigned aq[8][4], const float* ptt,
                                             float* rp, int r0, int r1, int u, int g) {
    float c[NBN][4];
    #pragma unroll
    for (int n = 0; n < NBN; n++) { c[n][0]=0.f; c[n][1]=0.f; c[n][2]=0.f; c[n][3]=0.f; }
    #pragma unroll
    for (int s = 0; s < 8; s++) {
        #pragma unroll
        for (int n = 0; n < NBN; n++) {
            int jr = (NB0 + n) * 8 + g;
            unsigned b0 = __float_as_uint(ptt[(8*s + u)     * PT_STRIDE + jr]);
            unsigned b1 = __float_as_uint(ptt[(8*s + u + 4) * PT_STRIDE + jr]);
            mma_tf32(c[n], aq[s], b0, b1);
        }
    }
    #pragma unroll
    for (int n = 0; n < NBN; n++) {
        int col = (NB0 + n) * 8 + 2 * u;
        if (col <= 128) {
            rp[r0*RP_STRIDE + col] = fmaf(c[n][0], 0.125f, -16.f);
            rp[r1*RP_STRIDE + col] = fmaf(c[n][2], 0.125f, -16.f);
        }
        if (col + 1 <= 128) {
            rp[r0*RP_STRIDE + col + 1] = fmaf(c[n][1], 0.125f, -16.f);
            rp[r1*RP_STRIDE + col + 1] = fmaf(c[n][3], 0.125f, -16.f);
        }
    }
}

__global__ void __launch_bounds__(NT, 2)
attn_tc_kernel(const float* __restrict__ q,
               const float* __restrict__ k,
               const float* __restrict__ v,
               const int* __restrict__ mask,
               const float* __restrict__ pt,
               float* __restrict__ out) {
    extern __shared__ float sm[];
    float* ks  = sm + KS_OFF;
    float* rp  = sm + RP_OFF;
    float* ptt = sm + PT_OFF;

    const int tid  = threadIdx.x;
    const int lane = tid & 31;
    const int w    = tid >> 5;
    const int u    = lane & 3;
    const int g    = lane >> 2;
    const int qt   = blockIdx.x, b = blockIdx.y;
    const int qg0  = qt * TQ;
    const int r0   = 16 * w + g;
    const int r1   = r0 + 8;
    const int keysel = (g >> 1) + 4 * (g & 1);   // sigma(g)

    const float4* kg = (const float4*)(k + (size_t)b * SS * DD);
    const float4* vg = (const float4*)(v + (size_t)b * SS * DD);
    const int* mrow0 = mask + (size_t)(b * SS + qg0 + r0) * SS;
    const int* mrow1 = mask + (size_t)(b * SS + qg0 + r1) * SS;

    // ---- phase 0: stage transposed tf32 pos_table (aliases K/V region) ----
    {
        const float4* ptg = (const float4*)pt;
        for (int i = tid; i < 129 * 16; i += NT) {
            int j = i >> 4, c0 = (i & 15) * 4;
            float4 p4 = ptg[i];
            ptt[(c0 + 0) * PT_STRIDE + j] = __uint_as_float(f2tf(p4.x));
            ptt[(c0 + 1) * PT_STRIDE + j] = __uint_as_float(f2tf(p4.y));
            ptt[(c0 + 2) * PT_STRIDE + j] = __uint_as_float(f2tf(p4.z));
            ptt[(c0 + 3) * PT_STRIDE + j] = __uint_as_float(f2tf(p4.w));
        }
        for (int i = tid; i < 64 * 7; i += NT)
            ptt[(i / 7) * PT_STRIDE + 129 + (i % 7)] = 0.f;
    }

    // ---- Q fragments straight from gmem ----
    unsigned aq[8][4];
    {
        const float* q0 = q + (size_t)(b * SS + qg0 + r0) * DD;
        const float* q1 = q + (size_t)(b * SS + qg0 + r1) * DD;
        #pragma unroll
        for (int s = 0; s < 8; s++) {
            aq[s][0] = f2tf(q0[8*s + u]);
            aq[s][1] = f2tf(q1[8*s + u]);
            aq[s][2] = f2tf(q0[8*s + u + 4]);
            aq[s][3] = f2tf(q1[8*s + u + 4]);
        }
    }
    __syncthreads();

    // ---- phase 1: rp table via MMA (pre-scaled: *0.125 - 16) ----
    rp_mma_chunk<0, 9>(aq, ptt, rp, r0, r1, u, g);
    rp_mma_chunk<9, 8>(aq, ptt, rp, r0, r1, u, g);
    __syncthreads();

    const float rpn0 = rp[r0 * RP_STRIDE + 0],   rpn1 = rp[r1 * RP_STRIDE + 0];
    const float rpp0 = rp[r0 * RP_STRIDE + 128], rpp1 = rp[r1 * RP_STRIDE + 128];

    // ---- prologue staging: cp.async V0 (raw), direct K0 (cvt+STS) ----
    {
        #pragma unroll
        for (int l = 0; l < 8; l++) {
            int i = tid + l * NT, row = i >> 4, c4 = i & 15;
            unsigned dst = (unsigned)__cvta_generic_to_shared(sm + VS0_OFF + row * VS_STRIDE + c4 * 4);
            cpa16(dst, vg + i);
        }
        CP_COMMIT();
        #pragma unroll
        for (int l = 0; l < 8; l++) {
            int i = tid + l * NT, row = i >> 4, c4 = i & 15;
            float4 kv = kg[i];
            float* kd = ks + row * KS_STRIDE + c4 * 4;
            kd[0] = __uint_as_float(f2tf(kv.x)); kd[1] = __uint_as_float(f2tf(kv.y));
            kd[2] = __uint_as_float(f2tf(kv.z)); kd[3] = __uint_as_float(f2tf(kv.w));
        }
        CP_WAIT(0);
    }
    __syncthreads();

    float ps0 = 0.f, ps1 = 0.f;    // per-thread softmax denominators
    float co[8][4];
    #pragma unroll
    for (int j = 0; j < 8; j++) { co[j][0]=0.f; co[j][1]=0.f; co[j][2]=0.f; co[j][3]=0.f; }

    float4 pk[8];

    for (int kt = 0; kt < SS / TK; kt++) {
        const int kg0 = kt * TK;
        const int D   = kg0 - qg0;
        const float* vcur = sm + ((kt & 1) ? VS1_OFF : VS0_OFF);

        // ---- mask LDGs for CURRENT tile (consumed after QK; latency hidden) ----
        int4 mm0[4], mm1[4];
        {
            const int4* p0 = (const int4*)(mrow0 + kg0) + 4 * u;
            const int4* p1 = (const int4*)(mrow1 + kg0) + 4 * u;
            #pragma unroll
            for (int l = 0; l < 4; l++) { mm0[l] = p0[l]; mm1[l] = p1[l]; }
        }

        // ---- issue next tile: V via cp.async, K into registers ----
        if (kt < 15) {
            float* vnext = sm + (((kt + 1) & 1) ? VS1_OFF : VS0_OFF);
            #pragma unroll
            for (int l = 0; l < 8; l++) {
                int i = tid + l * NT, row = i >> 4, c4 = i & 15;
                unsigned dst = (unsigned)__cvta_generic_to_shared(vnext + row * VS_STRIDE + c4 * 4);
                cpa16(dst, vg + (kg0 + TK) * 16 + i);
            }
            #pragma unroll
            for (int l = 0; l < 8; l++)
                pk[l] = kg[(kg0 + TK) * 16 + tid + l * NT];
        }
        CP_COMMIT();

        // ---- QK^T from staged K ----
        float c[8][4];
        #pragma unroll
        for (int j = 0; j < 8; j++) { c[j][0]=0.f; c[j][1]=0.f; c[j][2]=0.f; c[j][3]=0.f; }
        #pragma unroll
        for (int s = 0; s < 8; s++) {
            #pragma unroll
            for (int j = 0; j < 8; j++) {
                unsigned b0 = __float_as_uint(ks[(8*j + keysel) * KS_STRIDE + 8*s + u]);
                unsigned b1 = __float_as_uint(ks[(8*j + keysel) * KS_STRIDE + 8*s + u + 4]);
                mma_tf32(c[j], aq[s], b0, b1);
            }
        }

        // ---- assemble mask words via quad shuffles ----
        unsigned mw0a, mw0b, mw1a, mw1b;
        {
            unsigned b0 = pack16(mm0) << ((u & 1) * 16);
            unsigned b1 = pack16(mm1) << ((u & 1) * 16);
            b0 |= __shfl_xor_sync(0xffffffffu, b0, 1);
            b1 |= __shfl_xor_sync(0xffffffffu, b1, 1);
            unsigned o0 = __shfl_xor_sync(0xffffffffu, b0, 2);
            unsigned o1 = __shfl_xor_sync(0xffffffffu, b1, 2);
            mw0a = (u & 2) ? o0 : b0;  mw0b = (u & 2) ? b0 : o0;
            mw1a = (u & 2) ? o1 : b1;  mw1b = (u & 2) ? b1 : o1;
        }

        // ---- epilogue: p = exp(dot*0.125 + rp')   [rp' has -16 folded in] ----
        const bool nearT = (D >= -64) && (D <= 64);
        #pragma unroll
        for (int j = 0; j < 8; j++) {
            const int col0 = 8*j + u, col1 = col0 + 4;
            float rv00, rv01, rv10, rv11;
            if (nearT) {
                int i00 = min(max(D + col0 - r0, -64), 64) + 64;
                int i01 = min(max(D + col1 - r0, -64), 64) + 64;
                int i10 = min(max(D + col0 - r1, -64), 64) + 64;
                int i11 = min(max(D + col1 - r1, -64), 64) + 64;
                rv00 = rp[r0 * RP_STRIDE + i00]; rv01 = rp[r0 * RP_STRIDE + i01];
                rv10 = rp[r1 * RP_STRIDE + i10]; rv11 = rp[r1 * RP_STRIDE + i11];
            } else if (D > 0) {
                rv00 = rpp0; rv01 = rpp0; rv10 = rpp1; rv11 = rpp1;
            } else {
                rv00 = rpn0; rv01 = rpn0; rv10 = rpn1; rv11 = rpn1;
            }
            const unsigned w0 = (j < 4) ? mw0a : mw0b;
            const unsigned w1 = (j < 4) ? mw1a : mw1b;
            float p00 = ((w0 >> (col0 & 31)) & 1) ? 0.f : __expf(fmaf(c[j][0], 0.125f, rv00));
            float p01 = ((w0 >> (col1 & 31)) & 1) ? 0.f : __expf(fmaf(c[j][1], 0.125f, rv01));
            float p10 = ((w1 >> (col0 & 31)) & 1) ? 0.f : __expf(fmaf(c[j][2], 0.125f, rv10));
            float p11 = ((w1 >> (col1 & 31)) & 1) ? 0.f : __expf(fmaf(c[j][3], 0.125f, rv11));
            ps0 += p00 + p01;
            ps1 += p10 + p11;
            c[j][0] = p00; c[j][1] = p01; c[j][2] = p10; c[j][3] = p11;
        }

        // ---- V[kt] landed; make visible; stage K[kt+1] from prefetch regs ----
        CP_WAIT(1);
        __syncthreads();
        if (kt < 15) {
            #pragma unroll
            for (int l = 0; l < 8; l++) {
                int i = tid + l * NT, row = i >> 4, c4 = i & 15;
                float* kd = ks + row * KS_STRIDE + c4 * 4;
                kd[0] = __uint_as_float(f2tf(pk[l].x)); kd[1] = __uint_as_float(f2tf(pk[l].y));
                kd[2] = __uint_as_float(f2tf(pk[l].z)); kd[3] = __uint_as_float(f2tf(pk[l].w));
            }
        }

        // ---- PV: A frags renamed from P; V converted at fragment load ----
        #pragma unroll
        for (int s = 0; s < 8; s++) {
            unsigned a[4] = { f2tf(c[s][0]), f2tf(c[s][2]), f2tf(c[s][1]), f2tf(c[s][3]) };
            #pragma unroll
            for (int j = 0; j < 8; j++) {
                unsigned b0 = f2tf(vcur[(8*s + u)     * VS_STRIDE + 8*j + g]);
                unsigned b1 = f2tf(vcur[(8*s + u + 4) * VS_STRIDE + 8*j + g]);
                mma_tf32(co[j], a, b0, b1);
            }
        }
        __syncthreads();   // K STS visible before next QK; V buffer free for reuse
    }

    // ---- single softmax-denominator reduction (quad) ----
    ps0 += __shfl_xor_sync(0xffffffffu, ps0, 1);
    ps0 += __shfl_xor_sync(0xffffffffu, ps0, 2);
    ps1 += __shfl_xor_sync(0xffffffffu, ps1, 1);
    ps1 += __shfl_xor_sync(0xffffffffu, ps1, 2);

    // ---- finalize ----
    const float il0 = 1.0f / ps0, il1 = 1.0f / ps1;
    float* o0 = out + (size_t)(b * SS + qg0 + r0) * DD;
    float* o1 = out + (size_t)(b * SS + qg0 + r1) * DD;
    #pragma unroll
    for (int j = 0; j < 8; j++) {
        int col = 8*j + 2*u;
        float2 v0; v0.x = co[j][0] * il0; v0.y = co[j][1] * il0;
        float2 v1; v1.x = co[j][2] * il1; v1.y = co[j][3] * il1;
        *(float2*)(o0 + col) = v0;
        *(float2*)(o1 + col) = v1;
    }
}

extern "C" void kernel_launch(void* const* d_in, const int* in_sizes, int n_in,
                              void* d_out, int out_size) {
    const float* q    = (const float*)d_in[0];
    const float* k    = (const float*)d_in[1];
    const float* v    = (const float*)d_in[2];
    const int*   mask = (const int*)d_in[3];
    const float* pt   = (const float*)d_in[4];
    float*       out  = (float*)d_out;

    size_t smem = SMEM_FLOATS * sizeof(float);
    cudaFuncSetAttribute(attn_tc_kernel,
                         cudaFuncAttributeMaxDynamicSharedMemorySize, (int)smem);
    dim3 grid(SS / TQ, BB);
    attn_tc_kernel<<<grid, NT, smem>>>(q, k, v, mask, pt, out);
}